// round 5
// baseline (speedup 1.0000x reference)
#include <cuda_runtime.h>
#include <cuda_fp16.h>
#include <cstdint>

// Problem constants (fixed by the reference)
#define NN   100000      // nodes
#define EE   1600000     // edges
#define NCLI 1000000     // client table rows
#define DD   128         // feature dim (= H)
#define NB   98          // scan blocks = ceil(NN/1024)

// ---------------- scratch (static device globals; no allocation) -------------
__device__ __half g_Xh  [(size_t)NN * DD];  // layer-1 input (fp16)
__device__ __half g_Hh  [(size_t)NN * DD];  // layer-1 output (fp16)
__device__ __half g_AGGh[(size_t)NN * DD];  // neighbor mean (fp16)
__device__ int    g_deg[NN];
__device__ float  g_invdeg[NN];
__device__ int    g_rowptr[NN + 1];
__device__ int    g_pos[NN];
__device__ int    g_esrc[EE];
__device__ int    g_bsum[NB];
__device__ int    g_boff[NB];

// ---------------- helpers ----------------------------------------------------
__device__ __forceinline__ void mma_f16(float c[4],
                                        unsigned a0, unsigned a1, unsigned a2, unsigned a3,
                                        unsigned b0, unsigned b1) {
    asm volatile(
        "mma.sync.aligned.m16n8k16.row.col.f32.f16.f16.f32 "
        "{%0,%1,%2,%3}, {%4,%5,%6,%7}, {%8,%9}, {%0,%1,%2,%3};\n"
        : "+f"(c[0]), "+f"(c[1]), "+f"(c[2]), "+f"(c[3])
        : "r"(a0), "r"(a1), "r"(a2), "r"(a3), "r"(b0), "r"(b1));
}

// ---------------- kernels ----------------------------------------------------

// merged: warp-per-node embedding gather + thread-per-edge degree count
__global__ void k_embed_deg(const float* __restrict__ ctab,
                            const float* __restrict__ itab,
                            const int*   __restrict__ node_ids,
                            const int*   __restrict__ dst) {
    int tid  = blockIdx.x * blockDim.x + threadIdx.x;
    int gw   = tid >> 5;
    int lane = tid & 31;
    if (gw < NN) {
        int id = node_ids[gw];
        const float* src = (id < NCLI) ? (ctab + (size_t)id * DD)
                                       : (itab + (size_t)(id - NCLI) * DD);
        float4 v = *reinterpret_cast<const float4*>(src + lane * 4);
        __half2 p0 = __floats2half2_rn(v.x, v.y);
        __half2 p1 = __floats2half2_rn(v.z, v.w);
        uint2 pk = make_uint2(*(unsigned*)&p0, *(unsigned*)&p1);
        *reinterpret_cast<uint2*>(g_Xh + (size_t)gw * DD + lane * 4) = pk;
    }
    if (tid < EE) atomicAdd(&g_deg[dst[tid]], 1);
}

// ------- parallel 3-phase exclusive scan over degrees -------
__global__ void k_scan_part() {
    __shared__ int ws[32];
    int blk = blockIdx.x, tid = threadIdx.x;
    int lane = tid & 31, w = tid >> 5;
    int i = blk * 1024 + tid;
    int v = (i < NN) ? g_deg[i] : 0;
    int inc = v;
    #pragma unroll
    for (int off = 1; off < 32; off <<= 1) {
        int y = __shfl_up_sync(0xffffffffu, inc, off);
        if (lane >= off) inc += y;
    }
    if (lane == 31) ws[w] = inc;
    __syncthreads();
    if (w == 0) {
        int s = ws[lane];
        int inc2 = s;
        #pragma unroll
        for (int off = 1; off < 32; off <<= 1) {
            int y = __shfl_up_sync(0xffffffffu, inc2, off);
            if (lane >= off) inc2 += y;
        }
        ws[lane] = inc2 - s;
        if (lane == 31) g_bsum[blk] = inc2;
    }
    __syncthreads();
    if (i < NN) g_rowptr[i] = inc - v + ws[w];
}

__global__ void k_scan_bsum() {
    __shared__ int ws[4];
    int tid = threadIdx.x, lane = tid & 31, w = tid >> 5;
    int v = (tid < NB) ? g_bsum[tid] : 0;
    int inc = v;
    #pragma unroll
    for (int off = 1; off < 32; off <<= 1) {
        int y = __shfl_up_sync(0xffffffffu, inc, off);
        if (lane >= off) inc += y;
    }
    if (lane == 31) ws[w] = inc;
    __syncthreads();
    if (tid == 0) {
        int s = 0;
        #pragma unroll
        for (int j = 0; j < 4; ++j) { int t = ws[j]; ws[j] = s; s += t; }
    }
    __syncthreads();
    int excl = inc - v + ws[w];
    if (tid < NB) g_boff[tid] = excl;
    if (tid == NB - 1) g_rowptr[NN] = excl + v;
}

__global__ void k_scan_fin() {
    int blk = blockIdx.x;
    int i = blk * 1024 + threadIdx.x;
    if (i >= NN) return;
    int rp = g_rowptr[i] + g_boff[blk];
    g_rowptr[i] = rp;
    g_pos[i]    = rp;
    int d = g_deg[i];
    g_invdeg[i] = 1.0f / (float)(d > 0 ? d : 1);
}

__global__ void k_scatter(const int* __restrict__ src, const int* __restrict__ dst) {
    int e = blockIdx.x * blockDim.x + threadIdx.x;
    if (e >= EE) return;
    int d = dst[e];
    int p = atomicAdd(&g_pos[d], 1);
    g_esrc[p] = src[e];
}

// 16-lane group per node: mean over in-neighbors (CSR).
// uint4 (16B) row loads: 16 lanes x 8 halves = full 256B row.
__global__ void k_agg(int sel_x) {
    int g  = (blockIdx.x * blockDim.x + threadIdx.x) >> 4;
    int gl = threadIdx.x & 15;
    if (g >= NN) return;
    const __half* __restrict__ X = sel_x ? g_Hh : g_Xh;
    int s = g_rowptr[g], e = g_rowptr[g + 1];
    float a0 = 0.f, a1 = 0.f, a2 = 0.f, a3 = 0.f,
          a4 = 0.f, a5 = 0.f, a6 = 0.f, a7 = 0.f;
    const size_t coff = (size_t)gl * 8;
    #define ACC4(u) { \
        float2 f0 = __half22float2(*reinterpret_cast<const __half2*>(&(u).x)); \
        float2 f1 = __half22float2(*reinterpret_cast<const __half2*>(&(u).y)); \
        float2 f2 = __half22float2(*reinterpret_cast<const __half2*>(&(u).z)); \
        float2 f3 = __half22float2(*reinterpret_cast<const __half2*>(&(u).w)); \
        a0 += f0.x; a1 += f0.y; a2 += f1.x; a3 += f1.y; \
        a4 += f2.x; a5 += f2.y; a6 += f3.x; a7 += f3.y; }
    int i = s;
    for (; i + 4 <= e; i += 4) {
        int s0 = g_esrc[i], s1 = g_esrc[i + 1], s2 = g_esrc[i + 2], s3 = g_esrc[i + 3];
        uint4 u0 = *reinterpret_cast<const uint4*>(X + (size_t)s0 * DD + coff);
        uint4 u1 = *reinterpret_cast<const uint4*>(X + (size_t)s1 * DD + coff);
        uint4 u2 = *reinterpret_cast<const uint4*>(X + (size_t)s2 * DD + coff);
        uint4 u3 = *reinterpret_cast<const uint4*>(X + (size_t)s3 * DD + coff);
        ACC4(u0) ACC4(u1) ACC4(u2) ACC4(u3)
    }
    for (; i < e; ++i) {
        int s0 = g_esrc[i];
        uint4 u0 = *reinterpret_cast<const uint4*>(X + (size_t)s0 * DD + coff);
        ACC4(u0)
    }
    #undef ACC4
    float inv = g_invdeg[g];
    __half2 o0 = __floats2half2_rn(a0 * inv, a1 * inv);
    __half2 o1 = __floats2half2_rn(a2 * inv, a3 * inv);
    __half2 o2 = __floats2half2_rn(a4 * inv, a5 * inv);
    __half2 o3 = __floats2half2_rn(a6 * inv, a7 * inv);
    uint4 pk = make_uint4(*(unsigned*)&o0, *(unsigned*)&o1,
                          *(unsigned*)&o2, *(unsigned*)&o3);
    *reinterpret_cast<uint4*>(g_AGGh + (size_t)g * DD + coff) = pk;
}

// ---------------- fused GEMM: out = A @ Wself + AGG @ Wneigh + b (opt relu)
// fp16 mma.sync m16n8k16, fp32 accumulate, 32 rows per warp (two row-stacks
// share each B fragment -> half the LDS per FLOP). Weights transposed to
// [n][perm(k)] halves in smem; stride 144 -> conflict-free 16-lane phases.
#define WT_STRIDE 144                         // halves per n-row
#define GEMM_SMEM (2 * 128 * WT_STRIDE * 2)   // bytes

__device__ __forceinline__ void accum_panel2(const __half* __restrict__ A,
                                             const __half* __restrict__ Wt,
                                             float (*c0)[4], float (*c1)[4],
                                             int row0, int gid, int tig) {
    int ra0 = row0 + gid,      ra1 = row0 + gid + 8;
    int rb0 = row0 + gid + 16, rb1 = row0 + gid + 24;
    bool va0 = ra0 < NN, va1 = ra1 < NN, vb0 = rb0 < NN, vb1 = rb1 < NN;
    const __half* pa0 = A + (size_t)(va0 ? ra0 : 0) * DD;
    const __half* pa1 = A + (size_t)(va1 ? ra1 : 0) * DD;
    const __half* pb0 = A + (size_t)(vb0 ? rb0 : 0) * DD;
    const __half* pb1 = A + (size_t)(vb1 ? rb1 : 0) * DD;
    #pragma unroll
    for (int k0 = 0; k0 < 128; k0 += 16) {
        unsigned x0 = va0 ? *(const unsigned*)(pa0 + k0 + 2 * tig)     : 0u;
        unsigned x2 = va0 ? *(const unsigned*)(pa0 + k0 + 2 * tig + 8) : 0u;
        unsigned x1 = va1 ? *(const unsigned*)(pa1 + k0 + 2 * tig)     : 0u;
        unsigned x3 = va1 ? *(const unsigned*)(pa1 + k0 + 2 * tig + 8) : 0u;
        unsigned y0 = vb0 ? *(const unsigned*)(pb0 + k0 + 2 * tig)     : 0u;
        unsigned y2 = vb0 ? *(const unsigned*)(pb0 + k0 + 2 * tig + 8) : 0u;
        unsigned y1 = vb1 ? *(const unsigned*)(pb1 + k0 + 2 * tig)     : 0u;
        unsigned y3 = vb1 ? *(const unsigned*)(pb1 + k0 + 2 * tig + 8) : 0u;
        #pragma unroll
        for (int nt = 0; nt < 16; ++nt) {
            uint2 b = *reinterpret_cast<const uint2*>(
                Wt + (nt * 8 + gid) * WT_STRIDE + k0 + (tig << 2));
            mma_f16(c0[nt], x0, x1, x2, x3, b.x, b.y);
            mma_f16(c1[nt], y0, y1, y2, y3, b.x, b.y);
        }
    }
}

__global__ void __launch_bounds__(512, 1)
k_gemm(const float* __restrict__ Wself, const float* __restrict__ Wneigh,
       const float* __restrict__ bias, float* out_ext, int sel_x, int relu) {
    extern __shared__ __half smw[];
    __half* wt_self  = smw;
    __half* wt_neigh = smw + 128 * WT_STRIDE;

    int tid = threadIdx.x;
    // load + transpose + convert: W[k][n] -> Wt[n][perm(k)] (fp16)
    for (int idx = tid; idx < 128 * 128; idx += 512) {
        int k = idx >> 7, n = idx & 127;
        int k0 = k & ~15, kk = k & 15;
        int pos = (((kk & 7) >> 1) << 2) | ((kk >> 3) << 1) | (kk & 1);
        wt_self [n * WT_STRIDE + k0 + pos] = __float2half_rn(Wself [idx]);
        wt_neigh[n * WT_STRIDE + k0 + pos] = __float2half_rn(Wneigh[idx]);
    }
    __syncthreads();

    const __half* __restrict__ A = sel_x ? g_Hh : g_Xh;

    int warp = tid >> 5, lane = tid & 31;
    int gid = lane >> 2, tig = lane & 3;
    int row0 = blockIdx.x * 1024 + warp * 32;   // 512 threads = 16 warps * 32 rows... (grid sized below)

    float c0[16][4], c1[16][4];
    #pragma unroll
    for (int nt = 0; nt < 16; ++nt) {
        c0[nt][0] = c0[nt][1] = c0[nt][2] = c0[nt][3] = 0.f;
        c1[nt][0] = c1[nt][1] = c1[nt][2] = c1[nt][3] = 0.f;
    }

    // NOTE: block covers 16 warps * 32 rows = 512 rows
    row0 = blockIdx.x * 512 + warp * 32;

    accum_panel2(A,      wt_self,  c0, c1, row0, gid, tig);
    accum_panel2(g_AGGh, wt_neigh, c0, c1, row0, gid, tig);

    int r[4] = { row0 + gid, row0 + gid + 8, row0 + gid + 16, row0 + gid + 24 };
    #pragma unroll
    for (int nt = 0; nt < 16; ++nt) {
        int col = nt * 8 + 2 * tig;
        float bx = __ldg(bias + col), by = __ldg(bias + col + 1);
        float v[4][2] = {
            { c0[nt][0] + bx, c0[nt][1] + by },
            { c0[nt][2] + bx, c0[nt][3] + by },
            { c1[nt][0] + bx, c1[nt][1] + by },
            { c1[nt][2] + bx, c1[nt][3] + by } };
        #pragma unroll
        for (int q = 0; q < 4; ++q) {
            if (r[q] >= NN) continue;
            if (relu) {
                float w0 = fmaxf(v[q][0], 0.f), w1 = fmaxf(v[q][1], 0.f);
                __half2 p = __floats2half2_rn(w0, w1);
                *reinterpret_cast<unsigned*>(g_Hh + (size_t)r[q] * DD + col) = *(unsigned*)&p;
            } else {
                *reinterpret_cast<float2*>(out_ext + (size_t)r[q] * DD + col) =
                    make_float2(v[q][0], v[q][1]);
            }
        }
    }
}

// ---------------- launch -----------------------------------------------------
extern "C" void kernel_launch(void* const* d_in, const int* in_sizes, int n_in,
                              void* d_out, int out_size) {
    const float* ctab   = (const float*)d_in[0];
    const float* itab   = (const float*)d_in[1];
    const float* Wself1 = (const float*)d_in[2];
    const float* Wneigh1= (const float*)d_in[3];
    const float* b1     = (const float*)d_in[4];
    const float* Wself2 = (const float*)d_in[5];
    const float* Wneigh2= (const float*)d_in[6];
    const float* b2     = (const float*)d_in[7];
    const int*   nids   = (const int*)d_in[8];
    const int*   src    = (const int*)d_in[9];
    const int*   dst    = (const int*)d_in[10];
    float* out = (float*)d_out;

    cudaFuncSetAttribute(k_gemm, cudaFuncAttributeMaxDynamicSharedMemorySize, GEMM_SMEM);

    void* degp = nullptr;
    cudaGetSymbolAddress(&degp, g_deg);
    cudaMemsetAsync(degp, 0, NN * sizeof(int));

    const int ED_BLKS   = (NN * 32 + 255) / 256;   // covers both embed warps and edges
    const int EDGE_BLKS = (EE + 255) / 256;
    const int AGG_BLKS  = (NN * 16 + 255) / 256;
    const int GEMM_BLKS = (NN + 511) / 512;

    k_embed_deg<<<ED_BLKS, 256>>>(ctab, itab, nids, dst);
    k_scan_part<<<NB, 1024>>>();
    k_scan_bsum<<<1, 128>>>();
    k_scan_fin<<<NB, 1024>>>();
    k_scatter<<<EDGE_BLKS, 256>>>(src, dst);

    // layer 1
    k_agg<<<AGG_BLKS, 256>>>(0);
    k_gemm<<<GEMM_BLKS, 512, GEMM_SMEM>>>(Wself1, Wneigh1, b1, nullptr, 0, 1);
    // layer 2
    k_agg<<<AGG_BLKS, 256>>>(1);
    k_gemm<<<GEMM_BLKS, 512, GEMM_SMEM>>>(Wself2, Wneigh2, b2, out, 1, 0);
}

// round 7
// speedup vs baseline: 1.2716x; 1.2716x over previous
#include <cuda_runtime.h>
#include <cuda_fp16.h>
#include <cstdint>

// Problem constants (fixed by the reference)
#define NN   100000      // nodes
#define EE   1600000     // edges
#define NCLI 1000000     // client table rows
#define DD   128         // feature dim (= H)
#define NB   98          // scan blocks = ceil(NN/1024)

// ---------------- scratch (static device globals; no allocation) -------------
__device__ __half g_Xh  [(size_t)NN * DD];  // layer-1 input (fp16)
__device__ __half g_Hh  [(size_t)NN * DD];  // layer-1 output (fp16)
__device__ __half g_AGGh[(size_t)NN * DD];  // neighbor mean (fp16)
__device__ int    g_deg[NN];
__device__ float  g_invdeg[NN];
__device__ int    g_rowptr[NN + 1];
__device__ int    g_pos[NN];
__device__ int    g_esrc[EE];
__device__ int    g_bsum[NB];
__device__ int    g_boff[NB];

// ---------------- helpers ----------------------------------------------------
__device__ __forceinline__ void mma_f16(float c[4],
                                        unsigned a0, unsigned a1, unsigned a2, unsigned a3,
                                        unsigned b0, unsigned b1) {
    asm volatile(
        "mma.sync.aligned.m16n8k16.row.col.f32.f16.f16.f32 "
        "{%0,%1,%2,%3}, {%4,%5,%6,%7}, {%8,%9}, {%0,%1,%2,%3};\n"
        : "+f"(c[0]), "+f"(c[1]), "+f"(c[2]), "+f"(c[3])
        : "r"(a0), "r"(a1), "r"(a2), "r"(a3), "r"(b0), "r"(b1));
}

// ---------------- kernels ----------------------------------------------------

// merged: warp-per-node embedding gather + thread-per-edge degree count
__global__ void k_embed_deg(const float* __restrict__ ctab,
                            const float* __restrict__ itab,
                            const int*   __restrict__ node_ids,
                            const int*   __restrict__ dst) {
    int tid  = blockIdx.x * blockDim.x + threadIdx.x;
    int gw   = tid >> 5;
    int lane = tid & 31;
    if (gw < NN) {
        int id = node_ids[gw];
        const float* src = (id < NCLI) ? (ctab + (size_t)id * DD)
                                       : (itab + (size_t)(id - NCLI) * DD);
        float4 v = *reinterpret_cast<const float4*>(src + lane * 4);
        __half2 p0 = __floats2half2_rn(v.x, v.y);
        __half2 p1 = __floats2half2_rn(v.z, v.w);
        uint2 pk = make_uint2(*(unsigned*)&p0, *(unsigned*)&p1);
        *reinterpret_cast<uint2*>(g_Xh + (size_t)gw * DD + lane * 4) = pk;
    }
    if (tid < EE) atomicAdd(&g_deg[dst[tid]], 1);
}

// ------- parallel 3-phase exclusive scan over degrees -------
__global__ void k_scan_part() {
    __shared__ int ws[32];
    int blk = blockIdx.x, tid = threadIdx.x;
    int lane = tid & 31, w = tid >> 5;
    int i = blk * 1024 + tid;
    int v = (i < NN) ? g_deg[i] : 0;
    int inc = v;
    #pragma unroll
    for (int off = 1; off < 32; off <<= 1) {
        int y = __shfl_up_sync(0xffffffffu, inc, off);
        if (lane >= off) inc += y;
    }
    if (lane == 31) ws[w] = inc;
    __syncthreads();
    if (w == 0) {
        int s = ws[lane];
        int inc2 = s;
        #pragma unroll
        for (int off = 1; off < 32; off <<= 1) {
            int y = __shfl_up_sync(0xffffffffu, inc2, off);
            if (lane >= off) inc2 += y;
        }
        ws[lane] = inc2 - s;
        if (lane == 31) g_bsum[blk] = inc2;
    }
    __syncthreads();
    if (i < NN) g_rowptr[i] = inc - v + ws[w];
}

__global__ void k_scan_bsum() {
    __shared__ int ws[4];
    int tid = threadIdx.x, lane = tid & 31, w = tid >> 5;
    int v = (tid < NB) ? g_bsum[tid] : 0;
    int inc = v;
    #pragma unroll
    for (int off = 1; off < 32; off <<= 1) {
        int y = __shfl_up_sync(0xffffffffu, inc, off);
        if (lane >= off) inc += y;
    }
    if (lane == 31) ws[w] = inc;
    __syncthreads();
    if (tid == 0) {
        int s = 0;
        #pragma unroll
        for (int j = 0; j < 4; ++j) { int t = ws[j]; ws[j] = s; s += t; }
    }
    __syncthreads();
    int excl = inc - v + ws[w];
    if (tid < NB) g_boff[tid] = excl;
    if (tid == NB - 1) g_rowptr[NN] = excl + v;
}

__global__ void k_scan_fin() {
    int blk = blockIdx.x;
    int i = blk * 1024 + threadIdx.x;
    if (i >= NN) return;
    int rp = g_rowptr[i] + g_boff[blk];
    g_rowptr[i] = rp;
    g_pos[i]    = rp;
    int d = g_deg[i];
    g_invdeg[i] = 1.0f / (float)(d > 0 ? d : 1);
}

__global__ void k_scatter(const int* __restrict__ src, const int* __restrict__ dst) {
    int e = blockIdx.x * blockDim.x + threadIdx.x;
    if (e >= EE) return;
    int d = dst[e];
    int p = atomicAdd(&g_pos[d], 1);
    g_esrc[p] = src[e];
}

// 16-lane group per node: mean over in-neighbors (CSR).
// uint4 (16B) row loads: 16 lanes x 8 halves = full 256B row.
__global__ void k_agg(int sel_x) {
    int g  = (blockIdx.x * blockDim.x + threadIdx.x) >> 4;
    int gl = threadIdx.x & 15;
    if (g >= NN) return;
    const __half* __restrict__ X = sel_x ? g_Hh : g_Xh;
    int s = g_rowptr[g], e = g_rowptr[g + 1];
    float a0 = 0.f, a1 = 0.f, a2 = 0.f, a3 = 0.f,
          a4 = 0.f, a5 = 0.f, a6 = 0.f, a7 = 0.f;
    const size_t coff = (size_t)gl * 8;
    #define ACC4(u) { \
        float2 f0 = __half22float2(*reinterpret_cast<const __half2*>(&(u).x)); \
        float2 f1 = __half22float2(*reinterpret_cast<const __half2*>(&(u).y)); \
        float2 f2 = __half22float2(*reinterpret_cast<const __half2*>(&(u).z)); \
        float2 f3 = __half22float2(*reinterpret_cast<const __half2*>(&(u).w)); \
        a0 += f0.x; a1 += f0.y; a2 += f1.x; a3 += f1.y; \
        a4 += f2.x; a5 += f2.y; a6 += f3.x; a7 += f3.y; }
    int i = s;
    for (; i + 4 <= e; i += 4) {
        int s0 = g_esrc[i], s1 = g_esrc[i + 1], s2 = g_esrc[i + 2], s3 = g_esrc[i + 3];
        uint4 u0 = *reinterpret_cast<const uint4*>(X + (size_t)s0 * DD + coff);
        uint4 u1 = *reinterpret_cast<const uint4*>(X + (size_t)s1 * DD + coff);
        uint4 u2 = *reinterpret_cast<const uint4*>(X + (size_t)s2 * DD + coff);
        uint4 u3 = *reinterpret_cast<const uint4*>(X + (size_t)s3 * DD + coff);
        ACC4(u0) ACC4(u1) ACC4(u2) ACC4(u3)
    }
    for (; i < e; ++i) {
        int s0 = g_esrc[i];
        uint4 u0 = *reinterpret_cast<const uint4*>(X + (size_t)s0 * DD + coff);
        ACC4(u0)
    }
    #undef ACC4
    float inv = g_invdeg[g];
    __half2 o0 = __floats2half2_rn(a0 * inv, a1 * inv);
    __half2 o1 = __floats2half2_rn(a2 * inv, a3 * inv);
    __half2 o2 = __floats2half2_rn(a4 * inv, a5 * inv);
    __half2 o3 = __floats2half2_rn(a6 * inv, a7 * inv);
    uint4 pk = make_uint4(*(unsigned*)&o0, *(unsigned*)&o1,
                          *(unsigned*)&o2, *(unsigned*)&o3);
    *reinterpret_cast<uint4*>(g_AGGh + (size_t)g * DD + coff) = pk;
}

// ---------------- fused GEMM: out = A @ Wself + AGG @ Wneigh + b (opt relu)
// fp16 mma.sync m16n8k16, fp32 accumulate, 16 rows/warp (round-4 proven shape:
// 64 accumulators, ~100 regs, no spill at 512 threads). Weights transposed to
// [n][perm(k)] halves in smem; stride 144 -> conflict-free 16-lane phases.
#define WT_STRIDE 144                         // halves per n-row
#define GEMM_SMEM (2 * 128 * WT_STRIDE * 2)   // bytes

__device__ __forceinline__ void accum_panel(const __half* __restrict__ A,
                                            const __half* __restrict__ Wt,
                                            float (*c)[4], int row0, int gid, int tig) {
    int r0 = row0 + gid, r1 = row0 + gid + 8;
    bool v0 = r0 < NN, v1 = r1 < NN;
    const __half* a0p = A + (size_t)(v0 ? r0 : 0) * DD;
    const __half* a1p = A + (size_t)(v1 ? r1 : 0) * DD;
    #pragma unroll
    for (int k0 = 0; k0 < 128; k0 += 16) {
        unsigned a0 = v0 ? *(const unsigned*)(a0p + k0 + 2 * tig)     : 0u;
        unsigned a2 = v0 ? *(const unsigned*)(a0p + k0 + 2 * tig + 8) : 0u;
        unsigned a1 = v1 ? *(const unsigned*)(a1p + k0 + 2 * tig)     : 0u;
        unsigned a3 = v1 ? *(const unsigned*)(a1p + k0 + 2 * tig + 8) : 0u;
        #pragma unroll
        for (int nt = 0; nt < 16; ++nt) {
            uint2 b = *reinterpret_cast<const uint2*>(
                Wt + (nt * 8 + gid) * WT_STRIDE + k0 + (tig << 2));
            mma_f16(c[nt], a0, a1, a2, a3, b.x, b.y);
        }
    }
}

__global__ void __launch_bounds__(512, 1)
k_gemm(const float* __restrict__ Wself, const float* __restrict__ Wneigh,
       const float* __restrict__ bias, float* out_ext, int sel_x, int relu) {
    extern __shared__ __half smw[];
    __half* wt_self  = smw;
    __half* wt_neigh = smw + 128 * WT_STRIDE;

    int tid = threadIdx.x;
    // load + transpose + convert: W[k][n] -> Wt[n][perm(k)] (fp16)
    for (int idx = tid; idx < 128 * 128; idx += 512) {
        int k = idx >> 7, n = idx & 127;
        int k0 = k & ~15, kk = k & 15;
        int pos = (((kk & 7) >> 1) << 2) | ((kk >> 3) << 1) | (kk & 1);
        wt_self [n * WT_STRIDE + k0 + pos] = __float2half_rn(Wself [idx]);
        wt_neigh[n * WT_STRIDE + k0 + pos] = __float2half_rn(Wneigh[idx]);
    }
    __syncthreads();

    const __half* __restrict__ A = sel_x ? g_Hh : g_Xh;

    int warp = tid >> 5, lane = tid & 31;
    int gid = lane >> 2, tig = lane & 3;
    int row0 = blockIdx.x * 256 + warp * 16;

    float c[16][4];
    #pragma unroll
    for (int nt = 0; nt < 16; ++nt)
        c[nt][0] = c[nt][1] = c[nt][2] = c[nt][3] = 0.f;

    accum_panel(A,      wt_self,  c, row0, gid, tig);
    accum_panel(g_AGGh, wt_neigh, c, row0, gid, tig);

    int r0 = row0 + gid, r1 = row0 + gid + 8;
    #pragma unroll
    for (int nt = 0; nt < 16; ++nt) {
        int col = nt * 8 + 2 * tig;
        float bx = __ldg(bias + col), by = __ldg(bias + col + 1);
        float v0 = c[nt][0] + bx, v1 = c[nt][1] + by;
        float v2 = c[nt][2] + bx, v3 = c[nt][3] + by;
        if (relu) {   // layer 1: relu, fp16 shadow only
            v0 = fmaxf(v0, 0.f); v1 = fmaxf(v1, 0.f);
            v2 = fmaxf(v2, 0.f); v3 = fmaxf(v3, 0.f);
            if (r0 < NN) {
                __half2 p = __floats2half2_rn(v0, v1);
                *reinterpret_cast<unsigned*>(g_Hh + (size_t)r0 * DD + col) = *(unsigned*)&p;
            }
            if (r1 < NN) {
                __half2 p = __floats2half2_rn(v2, v3);
                *reinterpret_cast<unsigned*>(g_Hh + (size_t)r1 * DD + col) = *(unsigned*)&p;
            }
        } else {      // layer 2: fp32 final output
            if (r0 < NN)
                *reinterpret_cast<float2*>(out_ext + (size_t)r0 * DD + col) = make_float2(v0, v1);
            if (r1 < NN)
                *reinterpret_cast<float2*>(out_ext + (size_t)r1 * DD + col) = make_float2(v2, v3);
        }
    }
}

// ---------------- launch -----------------------------------------------------
extern "C" void kernel_launch(void* const* d_in, const int* in_sizes, int n_in,
                              void* d_out, int out_size) {
    const float* ctab   = (const float*)d_in[0];
    const float* itab   = (const float*)d_in[1];
    const float* Wself1 = (const float*)d_in[2];
    const float* Wneigh1= (const float*)d_in[3];
    const float* b1     = (const float*)d_in[4];
    const float* Wself2 = (const float*)d_in[5];
    const float* Wneigh2= (const float*)d_in[6];
    const float* b2     = (const float*)d_in[7];
    const int*   nids   = (const int*)d_in[8];
    const int*   src    = (const int*)d_in[9];
    const int*   dst    = (const int*)d_in[10];
    float* out = (float*)d_out;

    cudaFuncSetAttribute(k_gemm, cudaFuncAttributeMaxDynamicSharedMemorySize, GEMM_SMEM);

    void* degp = nullptr;
    cudaGetSymbolAddress(&degp, g_deg);
    cudaMemsetAsync(degp, 0, NN * sizeof(int));

    const int ED_BLKS   = (NN * 32 + 255) / 256;
    const int EDGE_BLKS = (EE + 255) / 256;
    const int AGG_BLKS  = (NN * 16 + 255) / 256;
    const int GEMM_BLKS = (NN + 255) / 256;

    k_embed_deg<<<ED_BLKS, 256>>>(ctab, itab, nids, dst);
    k_scan_part<<<NB, 1024>>>();
    k_scan_bsum<<<1, 128>>>();
    k_scan_fin<<<NB, 1024>>>();
    k_scatter<<<EDGE_BLKS, 256>>>(src, dst);

    // layer 1
    k_agg<<<AGG_BLKS, 256>>>(0);
    k_gemm<<<GEMM_BLKS, 512, GEMM_SMEM>>>(Wself1, Wneigh1, b1, nullptr, 0, 1);
    // layer 2
    k_agg<<<AGG_BLKS, 256>>>(1);
    k_gemm<<<GEMM_BLKS, 512, GEMM_SMEM>>>(Wself2, Wneigh2, b2, out, 1, 0);
}